// round 1
// baseline (speedup 1.0000x reference)
#include <cuda_runtime.h>

// Problem constants
#define Bb   256
#define Nn   128
#define Dd   2048
#define DH   128
#define Mtot (Bb*Nn)   // 32768 rows

// Scratch (device globals — no allocations allowed)
__device__ float g_h[(size_t)Mtot * DH];   // 16.8 MB
__device__ float g_t1[Mtot];
__device__ float g_t2[Mtot];

// ---------------- GEMM: g_h = X[32768,2048] @ Wa[2048,128] (fp32, f32x2 packed FMA) ----------------
#define BM 128
#define BN 128
#define BK 16
#define TM 8
#define TN 16
#define NTHREADS 128   // (BM/TM)=16 m-groups * (BN/TN)=8 n-groups

__device__ __forceinline__ unsigned long long dup_f32(float x) {
    unsigned long long u;
    asm("mov.b64 %0, {%1, %1};" : "=l"(u) : "f"(x));
    return u;
}
__device__ __forceinline__ void ffma2(unsigned long long& d, unsigned long long a, unsigned long long b) {
    asm("fma.rn.f32x2 %0, %1, %2, %0;" : "+l"(d) : "l"(a), "l"(b));
}

__global__ void __launch_bounds__(NTHREADS, 2)
gemm_h_kernel(const float* __restrict__ A, const float* __restrict__ W)
{
    // As padded by 4 floats/row: removes 4-way bank conflicts on transposed stores,
    // keeps 16B alignment for float4 inner loads (132*4 = 528 bytes ≡ 0 mod 16).
    __shared__ float As[BK][BM + 4];
    __shared__ float Bs[BK][BN];

    const int tid  = threadIdx.x;
    const int lane = tid & 31;
    const int warp = tid >> 5;

    // Each warp owns 32 m-rows; lane -> (m-group, n-group).
    const int tm = warp * 32 + (lane >> 3) * TM;   // m offset, multiple of 8
    const int ng = lane & 7;                        // n-group 0..7
    const int tn = ng * TN;                         // n offset, multiple of 16

    const float* Ab = A + (size_t)blockIdx.x * BM * Dd;

    unsigned long long acc[TM][TN / 2];
    #pragma unroll
    for (int i = 0; i < TM; i++)
        #pragma unroll
        for (int j = 0; j < TN / 2; j++) acc[i][j] = 0ull;

    const unsigned sBs = (unsigned)__cvta_generic_to_shared(&Bs[0][0]);

    float4 pa[4], pb[4];
    // Prefetch tile 0
    #pragma unroll
    for (int i = 0; i < 4; i++) {
        int f = tid + i * NTHREADS;
        int r = f >> 2, c = f & 3;                 // A: 4 float4 per 16-wide row
        pa[i] = *reinterpret_cast<const float4*>(Ab + (size_t)r * Dd + c * 4);
        int rb = f >> 5, cb = f & 31;              // B: 32 float4 per 128-wide row
        pb[i] = *reinterpret_cast<const float4*>(W + rb * BN + cb * 4);
    }

    const int ntiles = Dd / BK;  // 128
    for (int t = 0; t < ntiles; ++t) {
        // Commit prefetched tile to smem
        #pragma unroll
        for (int i = 0; i < 4; i++) {
            int f = tid + i * NTHREADS;
            int r = f >> 2, c = f & 3;
            As[c * 4 + 0][r] = pa[i].x;
            As[c * 4 + 1][r] = pa[i].y;
            As[c * 4 + 2][r] = pa[i].z;
            As[c * 4 + 3][r] = pa[i].w;
            int rb = f >> 5, cb = f & 31;
            *reinterpret_cast<float4*>(&Bs[rb][cb * 4]) = pb[i];
        }
        __syncthreads();

        // Prefetch next tile (global; overlaps with compute below)
        if (t + 1 < ntiles) {
            const float* An = Ab + (t + 1) * BK;
            const float* Wn = W + (size_t)(t + 1) * BK * BN;
            #pragma unroll
            for (int i = 0; i < 4; i++) {
                int f = tid + i * NTHREADS;
                int r = f >> 2, c = f & 3;
                pa[i] = *reinterpret_cast<const float4*>(An + (size_t)r * Dd + c * 4);
                int rb = f >> 5, cb = f & 31;
                pb[i] = *reinterpret_cast<const float4*>(Wn + rb * BN + cb * 4);
            }
        }

        // Compute: 16 k-steps, 8x16 micro-tile via packed f32x2 FMA
        #pragma unroll
        for (int k = 0; k < BK; k++) {
            float4 a0 = *reinterpret_cast<const float4*>(&As[k][tm]);
            float4 a1 = *reinterpret_cast<const float4*>(&As[k][tm + 4]);
            unsigned long long ad[8];
            ad[0] = dup_f32(a0.x); ad[1] = dup_f32(a0.y);
            ad[2] = dup_f32(a0.z); ad[3] = dup_f32(a0.w);
            ad[4] = dup_f32(a1.x); ad[5] = dup_f32(a1.y);
            ad[6] = dup_f32(a1.z); ad[7] = dup_f32(a1.w);

            // 16 b-values as 8 packed pairs; XOR-swizzled chunk order avoids
            // the 4-way conflict of the naive 64B-strided access.
            unsigned long long bp[8];
            #pragma unroll
            for (int j = 0; j < 4; j++) {
                int p = j ^ (ng >> 1);
                unsigned addr = sBs + (unsigned)((k * BN + tn + p * 4) * 4);
                asm volatile("ld.shared.v2.b64 {%0, %1}, [%2];"
                             : "=l"(bp[2 * p]), "=l"(bp[2 * p + 1]) : "r"(addr));
            }

            #pragma unroll
            for (int i = 0; i < TM; i++)
                #pragma unroll
                for (int j = 0; j < 8; j++)
                    ffma2(acc[i][j], ad[i], bp[j]);
        }
        __syncthreads();
    }

    // Epilogue: 8B stores (each u64 holds 2 adjacent fp32 outputs)
    float* Crow = g_h + (size_t)blockIdx.x * BM * DH;
    #pragma unroll
    for (int i = 0; i < TM; i++) {
        #pragma unroll
        for (int j = 0; j < 8; j++) {
            *reinterpret_cast<unsigned long long*>(
                &Crow[(size_t)(tm + i) * DH + tn + 2 * j]) = acc[i][j];
        }
    }
}

// ---------------- t1/t2: per-row 128-dot with Wb/Wc (one warp per row) ----------------
__global__ void t12_kernel(const float* __restrict__ Wb, const float* __restrict__ bb,
                           const float* __restrict__ Wc, const float* __restrict__ bc)
{
    int gwarp = (blockIdx.x * blockDim.x + threadIdx.x) >> 5;
    int lane  = threadIdx.x & 31;
    if (gwarp >= Mtot) return;
    const float4* hr  = reinterpret_cast<const float4*>(g_h + (size_t)gwarp * DH);
    const float4* wb4 = reinterpret_cast<const float4*>(Wb);
    const float4* wc4 = reinterpret_cast<const float4*>(Wc);
    float4 hv = hr[lane];
    float4 b4 = wb4[lane];
    float4 c4 = wc4[lane];
    float s1 = hv.x * b4.x + hv.y * b4.y + hv.z * b4.z + hv.w * b4.w;
    float s2 = hv.x * c4.x + hv.y * c4.y + hv.z * c4.z + hv.w * c4.w;
    #pragma unroll
    for (int off = 16; off; off >>= 1) {
        s1 += __shfl_xor_sync(0xffffffffu, s1, off);
        s2 += __shfl_xor_sync(0xffffffffu, s2, off);
    }
    if (lane == 0) {
        g_t1[gwarp] = s1 + bb[0];
        g_t2[gwarp] = s2 + bc[0];
    }
}

// ---------------- softmax(axis=i per (b,j) column) + fused epilogue ----------------
// out[b,i,j] = h*(1+coefs) + bias[j], coefs = softmax_i(leaky_relu(t1[b,i]+t2[b,j], 0.2))
__global__ void attn_out_kernel(const float* __restrict__ bias, float* __restrict__ out)
{
    __shared__ float s1[Nn];
    const int b = blockIdx.x;
    const int j = threadIdx.x;           // 0..127 (column of scores / DH index)
    s1[j] = g_t1[b * Nn + j];
    const float v2 = g_t2[b * Nn + j];
    const float bj = bias[j];
    __syncthreads();

    float m = -1e30f;
    #pragma unroll 4
    for (int i = 0; i < Nn; i++) {
        float s = s1[i] + v2;
        s = s > 0.f ? s : 0.2f * s;
        m = fmaxf(m, s);
    }
    float z = 0.f;
    #pragma unroll 4
    for (int i = 0; i < Nn; i++) {
        float s = s1[i] + v2;
        s = s > 0.f ? s : 0.2f * s;
        z += __expf(s - m);
    }
    const float rz = 1.f / z;

    const float* hb = g_h + (size_t)b * Nn * DH;
    float*       ob = out + (size_t)b * Nn * DH;
    #pragma unroll 2
    for (int i = 0; i < Nn; i++) {
        float s = s1[i] + v2;
        s = s > 0.f ? s : 0.2f * s;
        float c  = __expf(s - m) * rz;
        float hv = hb[i * DH + j];      // coalesced: consecutive j -> consecutive addr
        ob[i * DH + j] = fmaf(c, hv, hv + bj);
    }
}

// ---------------- launch ----------------
extern "C" void kernel_launch(void* const* d_in, const int* in_sizes, int n_in,
                              void* d_out, int out_size)
{
    const float* X    = (const float*)d_in[0];   // [256,128,2048]
    const float* Wa   = (const float*)d_in[1];   // [2048,128]
    const float* Wb   = (const float*)d_in[2];   // [128,1]
    const float* bb   = (const float*)d_in[3];   // [1]
    const float* Wc   = (const float*)d_in[4];   // [128,1]
    const float* bc   = (const float*)d_in[5];   // [1]
    const float* bias = (const float*)d_in[6];   // [128]
    float* out = (float*)d_out;

    gemm_h_kernel<<<Mtot / BM, NTHREADS>>>(X, Wa);
    t12_kernel<<<(Mtot * 32) / 256, 256>>>(Wb, bb, Wc, bc);
    attn_out_kernel<<<Bb, Nn>>>(bias, out);
}

// round 3
// speedup vs baseline: 12.6357x; 12.6357x over previous
#include <cuda_runtime.h>
#include <cuda.h>
#include <cuda_bf16.h>
#include <cstdint>

#define Bb   256
#define Nn   128
#define Dd   2048
#define DH   128
#define Mtot (Bb*Nn)   // 32768

// Scratch (device globals — no allocations allowed)
__device__ __align__(1024) float g_h[(size_t)Mtot * DH];                // 16.8 MB
__device__ __align__(1024) __nv_bfloat16 g_whi[(size_t)DH * Dd];        // W^T hi [n][k]
__device__ __align__(1024) __nv_bfloat16 g_wlo[(size_t)DH * Dd];        // W^T lo [n][k]
__device__ float g_t1[Mtot];
__device__ float g_t2[Mtot];

// ===================== PTX helpers =====================
__device__ __forceinline__ uint32_t smem_u32(const void* p) {
    uint32_t a;
    asm("{ .reg .u64 t; cvta.to.shared.u64 t, %1; cvt.u32.u64 %0, t; }" : "=r"(a) : "l"(p));
    return a;
}
__device__ __forceinline__ void mbar_init(uint32_t m, uint32_t cnt) {
    asm volatile("mbarrier.init.shared.b64 [%0], %1;" :: "r"(m), "r"(cnt) : "memory");
}
__device__ __forceinline__ void mbar_expect_tx(uint32_t m, uint32_t bytes) {
    asm volatile("mbarrier.arrive.expect_tx.shared.b64 _, [%0], %1;" :: "r"(m), "r"(bytes) : "memory");
}
__device__ __forceinline__ void mbar_wait(uint32_t m, uint32_t ph) {
    asm volatile(
        "{\n\t.reg .pred P;\n"
        "W%=:\n\t"
        "mbarrier.try_wait.parity.acquire.cta.shared::cta.b64 P, [%0], %1, 0x989680;\n\t"
        "@P bra D%=;\n\t"
        "bra W%=;\n"
        "D%=:\n\t}"
        :: "r"(m), "r"(ph) : "memory");
}
__device__ __forceinline__ void tma2d(uint32_t dst, const CUtensorMap* map, int x, int y, uint32_t mbar) {
    asm volatile(
        "cp.async.bulk.tensor.2d.shared::cta.global.tile.mbarrier::complete_tx::bytes "
        "[%0], [%1, {%2, %3}], [%4];"
        :: "r"(dst), "l"(map), "r"(x), "r"(y), "r"(mbar) : "memory");
}
__device__ __forceinline__ void mma16816(float* d, const uint32_t* a, uint32_t b0, uint32_t b1) {
    asm volatile(
        "mma.sync.aligned.m16n8k16.row.col.f32.bf16.bf16.f32 "
        "{%0,%1,%2,%3}, {%4,%5,%6,%7}, {%8,%9}, {%0,%1,%2,%3};"
        : "+f"(d[0]), "+f"(d[1]), "+f"(d[2]), "+f"(d[3])
        : "r"(a[0]), "r"(a[1]), "r"(a[2]), "r"(a[3]), "r"(b0), "r"(b1));
}

// ===================== GEMM config =====================
#define KC        32                      // K elems per tile
#define NTILE     (Dd / KC)               // 64
#define FPA_STAGE (128 * KC * 4)          // 16384 B fp32 A tile
#define BROW      80                      // padded bf16 row stride (conflict-free: g*20+tig perm)
#define BFA       (128 * BROW)            // 10240 B per bf16 tile
#define OFF_FPA   1024
#define OFF_AH    (OFF_FPA + 3 * FPA_STAGE)     // 50176
#define OFF_AL    (OFF_AH + 2 * BFA)            // 70656
#define OFF_BH    (OFF_AL + 2 * BFA)            // 91136
#define OFF_BL    (OFF_BH + 2 * BFA)            // 111616
#define SMEMSZ    (OFF_BL + 2 * BFA)            // 132096

__global__ void __launch_bounds__(256, 1)
gemm_bf16x3(const __grid_constant__ CUtensorMap mapA)
{
    extern __shared__ char smem[];
    const uint32_t sb = smem_u32(smem);
    const int tid = threadIdx.x;
    const int lane = tid & 31, w = tid >> 5;
    const int g = lane >> 2, tig = lane & 3;
    const int wm = w & 3;        // m-block (32 rows each)
    const int wn = w >> 2;       // n-block (64 cols each)

    if (tid == 0) { mbar_init(sb + 0, 1); mbar_init(sb + 8, 1); mbar_init(sb + 16, 1); }
    __syncthreads();

    if (tid == 0) {
        #pragma unroll
        for (int s = 0; s < 3; s++) {
            mbar_expect_tx(sb + 8 * s, FPA_STAGE);
            tma2d(sb + OFF_FPA + s * FPA_STAGE, &mapA, s * KC, blockIdx.x * 128, sb + 8 * s);
        }
    }

    float acc[2][8][4];
    #pragma unroll
    for (int mt = 0; mt < 2; mt++)
        #pragma unroll
        for (int nt = 0; nt < 8; nt++)
            #pragma unroll
            for (int q = 0; q < 4; q++) acc[mt][nt][q] = 0.f;

    #pragma unroll 1
    for (int t = 0; t < NTILE; t++) {
        const int st = t % 3;
        const int buf = t & 1;
        const uint32_t ph = (t / 3) & 1;

        // --- B: global loads from pre-split weights (L2-resident, 16 KB/tile) ---
        float4 bhv[2], blv[2];
        #pragma unroll
        for (int i = 0; i < 2; i++) {
            int f = tid + i * 256;
            int n = f >> 2, kq = f & 3;
            size_t byt = (size_t)n * (Dd * 2) + (size_t)t * (KC * 2) + kq * 16;
            bhv[i] = *reinterpret_cast<const float4*>(reinterpret_cast<const char*>(g_whi) + byt);
            blv[i] = *reinterpret_cast<const float4*>(reinterpret_cast<const char*>(g_wlo) + byt);
        }

        // --- wait for fp32 A tile ---
        mbar_wait(sb + 8 * st, ph);

        // --- convert A fp32 -> bf16 hi/lo into padded SMEM ---
        const float4* fa = reinterpret_cast<const float4*>(smem + OFF_FPA + st * FPA_STAGE);
        #pragma unroll
        for (int i = 0; i < 4; i++) {
            int f = tid + i * 256;
            int m = f >> 3, kq = f & 7;
            float4 x = fa[f];
            __nv_bfloat162 h0 = __float22bfloat162_rn(make_float2(x.x, x.y));
            __nv_bfloat162 h1 = __float22bfloat162_rn(make_float2(x.z, x.w));
            float2 hf0 = __bfloat1622float2(h0);
            float2 hf1 = __bfloat1622float2(h1);
            __nv_bfloat162 l0 = __float22bfloat162_rn(make_float2(x.x - hf0.x, x.y - hf0.y));
            __nv_bfloat162 l1 = __float22bfloat162_rn(make_float2(x.z - hf1.x, x.w - hf1.y));
            uint32_t off = (uint32_t)m * BROW + (uint32_t)kq * 8;
            *reinterpret_cast<uint2*>(smem + OFF_AH + buf * BFA + off) =
                make_uint2(*reinterpret_cast<uint32_t*>(&h0), *reinterpret_cast<uint32_t*>(&h1));
            *reinterpret_cast<uint2*>(smem + OFF_AL + buf * BFA + off) =
                make_uint2(*reinterpret_cast<uint32_t*>(&l0), *reinterpret_cast<uint32_t*>(&l1));
        }
        // --- store B into padded SMEM ---
        #pragma unroll
        for (int i = 0; i < 2; i++) {
            int f = tid + i * 256;
            int n = f >> 2, kq = f & 3;
            uint32_t off = (uint32_t)n * BROW + (uint32_t)kq * 16;
            *reinterpret_cast<float4*>(smem + OFF_BH + buf * BFA + off) = bhv[i];
            *reinterpret_cast<float4*>(smem + OFF_BL + buf * BFA + off) = blv[i];
        }
        __syncthreads();

        // --- refill the fp32 stage we just consumed ---
        if (tid == 0 && t + 3 < NTILE) {
            mbar_expect_tx(sb + 8 * st, FPA_STAGE);
            tma2d(sb + OFF_FPA + st * FPA_STAGE, &mapA, (t + 3) * KC, blockIdx.x * 128, sb + 8 * st);
        }

        // --- MMA: 2 k16-steps, 2m x 8n tiles, 3 passes ---
        #pragma unroll
        for (int s = 0; s < 2; s++) {
            uint32_t ah[2][4], al[2][4];
            #pragma unroll
            for (int mt = 0; mt < 2; mt++) {
                const char* base = smem + OFF_AH + buf * BFA
                                 + (wm * 32 + mt * 16 + g) * BROW + s * 32 + tig * 4;
                ah[mt][0] = *reinterpret_cast<const uint32_t*>(base);
                ah[mt][1] = *reinterpret_cast<const uint32_t*>(base + 8 * BROW);
                ah[mt][2] = *reinterpret_cast<const uint32_t*>(base + 16);
                ah[mt][3] = *reinterpret_cast<const uint32_t*>(base + 8 * BROW + 16);
                const char* basl = base + (OFF_AL - OFF_AH);
                al[mt][0] = *reinterpret_cast<const uint32_t*>(basl);
                al[mt][1] = *reinterpret_cast<const uint32_t*>(basl + 8 * BROW);
                al[mt][2] = *reinterpret_cast<const uint32_t*>(basl + 16);
                al[mt][3] = *reinterpret_cast<const uint32_t*>(basl + 8 * BROW + 16);
            }
            #pragma unroll
            for (int nt = 0; nt < 8; nt++) {
                const char* nb = smem + OFF_BH + buf * BFA
                               + (wn * 64 + nt * 8 + g) * BROW + s * 32 + tig * 4;
                uint32_t bh0 = *reinterpret_cast<const uint32_t*>(nb);
                uint32_t bh1 = *reinterpret_cast<const uint32_t*>(nb + 16);
                const char* nl = nb + (OFF_BL - OFF_BH);
                uint32_t bl0 = *reinterpret_cast<const uint32_t*>(nl);
                uint32_t bl1 = *reinterpret_cast<const uint32_t*>(nl + 16);
                #pragma unroll
                for (int mt = 0; mt < 2; mt++) {
                    mma16816(acc[mt][nt], ah[mt], bh0, bh1);   // hi*hi
                    mma16816(acc[mt][nt], ah[mt], bl0, bl1);   // hi*lo
                    mma16816(acc[mt][nt], al[mt], bh0, bh1);   // lo*hi
                }
            }
        }
    }

    // --- epilogue: write h ---
    const int mbase = blockIdx.x * 128 + wm * 32;
    const int nbase = wn * 64;
    #pragma unroll
    for (int mt = 0; mt < 2; mt++) {
        #pragma unroll
        for (int nt = 0; nt < 8; nt++) {
            int r = mbase + mt * 16 + g;
            int c = nbase + nt * 8 + 2 * tig;
            *reinterpret_cast<float2*>(&g_h[(size_t)r * DH + c]) =
                make_float2(acc[mt][nt][0], acc[mt][nt][1]);
            *reinterpret_cast<float2*>(&g_h[(size_t)(r + 8) * DH + c]) =
                make_float2(acc[mt][nt][2], acc[mt][nt][3]);
        }
    }
}

// ===================== W transpose + bf16 hi/lo split =====================
__global__ void wsplit_kernel(const float* __restrict__ Wa)
{
    int idx = blockIdx.x * 256 + threadIdx.x;        // over DH*Dd, [n][k] order
    int n = idx >> 11, k = idx & 2047;
    float x = Wa[(size_t)k * DH + n];
    __nv_bfloat16 h = __float2bfloat16_rn(x);
    float hf = __bfloat162float(h);
    g_whi[idx] = h;
    g_wlo[idx] = __float2bfloat16_rn(x - hf);
}

// ===================== t1/t2 row dots =====================
__global__ void t12_kernel(const float* __restrict__ Wb, const float* __restrict__ bb,
                           const float* __restrict__ Wc, const float* __restrict__ bc)
{
    int gwarp = (blockIdx.x * blockDim.x + threadIdx.x) >> 5;
    int lane  = threadIdx.x & 31;
    if (gwarp >= Mtot) return;
    const float4* hr  = reinterpret_cast<const float4*>(g_h + (size_t)gwarp * DH);
    const float4* wb4 = reinterpret_cast<const float4*>(Wb);
    const float4* wc4 = reinterpret_cast<const float4*>(Wc);
    float4 hv = hr[lane];
    float4 b4 = wb4[lane];
    float4 c4 = wc4[lane];
    float s1 = hv.x * b4.x + hv.y * b4.y + hv.z * b4.z + hv.w * b4.w;
    float s2 = hv.x * c4.x + hv.y * c4.y + hv.z * c4.z + hv.w * c4.w;
    #pragma unroll
    for (int off = 16; off; off >>= 1) {
        s1 += __shfl_xor_sync(0xffffffffu, s1, off);
        s2 += __shfl_xor_sync(0xffffffffu, s2, off);
    }
    if (lane == 0) {
        g_t1[gwarp] = s1 + bb[0];
        g_t2[gwarp] = s2 + bc[0];
    }
}

// ===================== softmax(axis=i) + fused epilogue =====================
__global__ void attn_out_kernel(const float* __restrict__ bias, float* __restrict__ out)
{
    __shared__ float s1[Nn];
    const int b = blockIdx.x;
    const int j = threadIdx.x;
    s1[j] = g_t1[b * Nn + j];
    const float v2 = g_t2[b * Nn + j];
    const float bj = bias[j];
    __syncthreads();

    float mx = -1e30f;
    #pragma unroll 4
    for (int i = 0; i < Nn; i++) {
        float s = s1[i] + v2;
        s = s > 0.f ? s : 0.2f * s;
        mx = fmaxf(mx, s);
    }
    float z = 0.f;
    #pragma unroll 4
    for (int i = 0; i < Nn; i++) {
        float s = s1[i] + v2;
        s = s > 0.f ? s : 0.2f * s;
        z += __expf(s - mx);
    }
    const float rz = 1.f / z;

    const float* hb = g_h + (size_t)b * Nn * DH;
    float*       ob = out + (size_t)b * Nn * DH;
    #pragma unroll 2
    for (int i = 0; i < Nn; i++) {
        float s = s1[i] + v2;
        s = s > 0.f ? s : 0.2f * s;
        float c  = __expf(s - mx) * rz;
        float hv = hb[i * DH + j];
        ob[i * DH + j] = fmaf(c, hv, hv + bj);
    }
}

// ===================== launch =====================
typedef CUresult (*tmap_encode_t)(CUtensorMap*, CUtensorMapDataType, cuuint32_t, void*,
                                  const cuuint64_t*, const cuuint64_t*, const cuuint32_t*,
                                  const cuuint32_t*, CUtensorMapInterleave, CUtensorMapSwizzle,
                                  CUtensorMapL2promotion, CUtensorMapFloatOOBfill);

extern "C" void kernel_launch(void* const* d_in, const int* in_sizes, int n_in,
                              void* d_out, int out_size)
{
    const float* X    = (const float*)d_in[0];   // [256,128,2048]
    const float* Wa   = (const float*)d_in[1];   // [2048,128]
    const float* Wb   = (const float*)d_in[2];
    const float* bb   = (const float*)d_in[3];
    const float* Wc   = (const float*)d_in[4];
    const float* bc   = (const float*)d_in[5];
    const float* bias = (const float*)d_in[6];
    float* out = (float*)d_out;

    // TMA map for X: inner dim K (2048 fp32), outer M (32768); box [32, 128], no swizzle.
    tmap_encode_t enc = nullptr;
    cudaDriverEntryPointQueryResult qr;
    cudaGetDriverEntryPointByVersion("cuTensorMapEncodeTiled", (void**)&enc, 12000,
                                     cudaEnableDefault, &qr);
    CUtensorMap mapA;
    {
        cuuint64_t dims[2]    = {Dd, Mtot};
        cuuint64_t strides[1] = {Dd * sizeof(float)};
        cuuint32_t box[2]     = {KC, 128};
        cuuint32_t es[2]      = {1, 1};
        enc(&mapA, CU_TENSOR_MAP_DATA_TYPE_FLOAT32, 2, (void*)X, dims, strides, box, es,
            CU_TENSOR_MAP_INTERLEAVE_NONE, CU_TENSOR_MAP_SWIZZLE_NONE,
            CU_TENSOR_MAP_L2_PROMOTION_L2_128B, CU_TENSOR_MAP_FLOAT_OOB_FILL_NONE);
    }

    wsplit_kernel<<<(Dd * DH) / 256, 256>>>(Wa);

    cudaFuncSetAttribute(gemm_bf16x3, cudaFuncAttributeMaxDynamicSharedMemorySize, SMEMSZ);
    gemm_bf16x3<<<Mtot / 128, 256, SMEMSZ>>>(mapA);

    t12_kernel<<<(Mtot * 32) / 256, 256>>>(Wb, bb, Wc, bc);
    attn_out_kernel<<<Bb, Nn>>>(bias, out);
}

// round 4
// speedup vs baseline: 17.2184x; 1.3627x over previous
#include <cuda_runtime.h>
#include <cuda.h>
#include <cuda_bf16.h>
#include <cstdint>

#define Bb   256
#define Nn   128
#define Dd   2048
#define DH   128
#define Mtot (Bb*Nn)   // 32768

// Scratch (device globals — no allocations allowed)
__device__ __align__(1024) __nv_bfloat16 g_whi[(size_t)DH * Dd];   // W^T hi [n][k]
__device__ __align__(1024) __nv_bfloat16 g_wlo[(size_t)DH * Dd];   // W^T lo [n][k]

// ===================== PTX helpers =====================
__device__ __forceinline__ uint32_t smem_u32(const void* p) {
    uint32_t a;
    asm("{ .reg .u64 t; cvta.to.shared.u64 t, %1; cvt.u32.u64 %0, t; }" : "=r"(a) : "l"(p));
    return a;
}
__device__ __forceinline__ void mbar_init(uint32_t m, uint32_t cnt) {
    asm volatile("mbarrier.init.shared.b64 [%0], %1;" :: "r"(m), "r"(cnt) : "memory");
}
__device__ __forceinline__ void mbar_expect_tx(uint32_t m, uint32_t bytes) {
    asm volatile("mbarrier.arrive.expect_tx.shared.b64 _, [%0], %1;" :: "r"(m), "r"(bytes) : "memory");
}
__device__ __forceinline__ void mbar_wait(uint32_t m, uint32_t ph) {
    asm volatile(
        "{\n\t.reg .pred P;\n"
        "W%=:\n\t"
        "mbarrier.try_wait.parity.acquire.cta.shared::cta.b64 P, [%0], %1, 0x989680;\n\t"
        "@P bra D%=;\n\t"
        "bra W%=;\n"
        "D%=:\n\t}"
        :: "r"(m), "r"(ph) : "memory");
}
__device__ __forceinline__ void tma2d(uint32_t dst, const CUtensorMap* map, int x, int y, uint32_t mbar) {
    asm volatile(
        "cp.async.bulk.tensor.2d.shared::cta.global.tile.mbarrier::complete_tx::bytes "
        "[%0], [%1, {%2, %3}], [%4];"
        :: "r"(dst), "l"(map), "r"(x), "r"(y), "r"(mbar) : "memory");
}
__device__ __forceinline__ void mma16816(float* d, const uint32_t* a, uint32_t b0, uint32_t b1) {
    asm volatile(
        "mma.sync.aligned.m16n8k16.row.col.f32.bf16.bf16.f32 "
        "{%0,%1,%2,%3}, {%4,%5,%6,%7}, {%8,%9}, {%0,%1,%2,%3};"
        : "+f"(d[0]), "+f"(d[1]), "+f"(d[2]), "+f"(d[3])
        : "r"(a[0]), "r"(a[1]), "r"(a[2]), "r"(a[3]), "r"(b0), "r"(b1));
}
__device__ __forceinline__ float lrelu(float s) { return s > 0.f ? s : 0.2f * s; }

// ===================== config =====================
#define KC        32
#define NTILE     (Dd / KC)               // 64
#define FPA_STAGE (128 * KC * 4)          // 16384 B fp32 A tile
#define BROW      80                      // padded bf16 row stride, conflict-free
#define BFA       (128 * BROW)            // 10240 B per bf16 tile
#define OFF_FPA   1024
#define OFF_AH    (OFF_FPA + 2 * FPA_STAGE)   // 33792
#define OFF_AL    (OFF_AH + BFA)              // 44032
#define OFF_BH    (OFF_AL + BFA)              // 54272
#define OFF_BL    (OFF_BH + BFA)              // 64512
#define SMEMSZ    (OFF_BL + BFA)              // 74752 -> 2 CTAs/SM

__global__ void __launch_bounds__(256, 2)
fused_gat(const float* __restrict__ Wbv, const float* __restrict__ bbv,
          const float* __restrict__ Wcv, const float* __restrict__ bcv,
          const float* __restrict__ bias, float* __restrict__ out,
          const __grid_constant__ CUtensorMap mapA)
{
    extern __shared__ char smem[];
    const uint32_t sb = smem_u32(smem);
    const int tid = threadIdx.x;
    const int lane = tid & 31, w = tid >> 5;
    const int g = lane >> 2, tig = lane & 3;
    const int wm = w & 3;        // m-block (32 rows)
    const int wn = w >> 2;       // n-block (64 cols)

    if (tid == 0) { mbar_init(sb + 0, 1); mbar_init(sb + 8, 1); }
    __syncthreads();
    if (tid == 0) {
        #pragma unroll
        for (int s = 0; s < 2; s++) {
            mbar_expect_tx(sb + 8 * s, FPA_STAGE);
            tma2d(sb + OFF_FPA + s * FPA_STAGE, &mapA, s * KC, blockIdx.x * 128, sb + 8 * s);
        }
    }

    float acc[2][8][4];
    #pragma unroll
    for (int mt = 0; mt < 2; mt++)
        #pragma unroll
        for (int nt = 0; nt < 8; nt++)
            #pragma unroll
            for (int q = 0; q < 4; q++) acc[mt][nt][q] = 0.f;

    #pragma unroll 1
    for (int t = 0; t < NTILE; t++) {
        const int st = t & 1;
        const uint32_t ph = (t >> 1) & 1;

        // B: global loads (L2-resident pre-split weights)
        float4 bhv[2], blv[2];
        #pragma unroll
        for (int i = 0; i < 2; i++) {
            int f = tid + i * 256;
            int n = f >> 2, kq = f & 3;
            size_t byt = (size_t)n * (Dd * 2) + (size_t)t * (KC * 2) + kq * 16;
            bhv[i] = *reinterpret_cast<const float4*>(reinterpret_cast<const char*>(g_whi) + byt);
            blv[i] = *reinterpret_cast<const float4*>(reinterpret_cast<const char*>(g_wlo) + byt);
        }

        mbar_wait(sb + 8 * st, ph);

        // convert A fp32 -> bf16 hi/lo
        const float4* fa = reinterpret_cast<const float4*>(smem + OFF_FPA + st * FPA_STAGE);
        #pragma unroll
        for (int i = 0; i < 4; i++) {
            int f = tid + i * 256;
            int m = f >> 3, kq = f & 7;
            float4 x = fa[f];
            __nv_bfloat162 h0 = __float22bfloat162_rn(make_float2(x.x, x.y));
            __nv_bfloat162 h1 = __float22bfloat162_rn(make_float2(x.z, x.w));
            float2 hf0 = __bfloat1622float2(h0);
            float2 hf1 = __bfloat1622float2(h1);
            __nv_bfloat162 l0 = __float22bfloat162_rn(make_float2(x.x - hf0.x, x.y - hf0.y));
            __nv_bfloat162 l1 = __float22bfloat162_rn(make_float2(x.z - hf1.x, x.w - hf1.y));
            uint32_t off = (uint32_t)m * BROW + (uint32_t)kq * 8;
            *reinterpret_cast<uint2*>(smem + OFF_AH + off) =
                make_uint2(*reinterpret_cast<uint32_t*>(&h0), *reinterpret_cast<uint32_t*>(&h1));
            *reinterpret_cast<uint2*>(smem + OFF_AL + off) =
                make_uint2(*reinterpret_cast<uint32_t*>(&l0), *reinterpret_cast<uint32_t*>(&l1));
        }
        #pragma unroll
        for (int i = 0; i < 2; i++) {
            int f = tid + i * 256;
            int n = f >> 2, kq = f & 3;
            uint32_t off = (uint32_t)n * BROW + (uint32_t)kq * 16;
            *reinterpret_cast<float4*>(smem + OFF_BH + off) = bhv[i];
            *reinterpret_cast<float4*>(smem + OFF_BL + off) = blv[i];
        }
        __syncthreads();

        // refill the fp32 stage just consumed
        if (tid == 0 && t + 2 < NTILE) {
            mbar_expect_tx(sb + 8 * st, FPA_STAGE);
            tma2d(sb + OFF_FPA + st * FPA_STAGE, &mapA, (t + 2) * KC, blockIdx.x * 128, sb + 8 * st);
        }

        // MMA: 2 k16 steps, 2m x 8n, 3 passes
        #pragma unroll
        for (int s = 0; s < 2; s++) {
            uint32_t ah[2][4], al[2][4];
            #pragma unroll
            for (int mt = 0; mt < 2; mt++) {
                const char* base = smem + OFF_AH + (wm * 32 + mt * 16 + g) * BROW + s * 32 + tig * 4;
                ah[mt][0] = *reinterpret_cast<const uint32_t*>(base);
                ah[mt][1] = *reinterpret_cast<const uint32_t*>(base + 8 * BROW);
                ah[mt][2] = *reinterpret_cast<const uint32_t*>(base + 16);
                ah[mt][3] = *reinterpret_cast<const uint32_t*>(base + 8 * BROW + 16);
                const char* basl = base + (OFF_AL - OFF_AH);
                al[mt][0] = *reinterpret_cast<const uint32_t*>(basl);
                al[mt][1] = *reinterpret_cast<const uint32_t*>(basl + 8 * BROW);
                al[mt][2] = *reinterpret_cast<const uint32_t*>(basl + 16);
                al[mt][3] = *reinterpret_cast<const uint32_t*>(basl + 8 * BROW + 16);
            }
            #pragma unroll
            for (int nt = 0; nt < 8; nt++) {
                const char* nb = smem + OFF_BH + (wn * 64 + nt * 8 + g) * BROW + s * 32 + tig * 4;
                uint32_t bh0 = *reinterpret_cast<const uint32_t*>(nb);
                uint32_t bh1 = *reinterpret_cast<const uint32_t*>(nb + 16);
                const char* nl = nb + (OFF_BL - OFF_BH);
                uint32_t bl0 = *reinterpret_cast<const uint32_t*>(nl);
                uint32_t bl1 = *reinterpret_cast<const uint32_t*>(nl + 16);
                #pragma unroll
                for (int mt = 0; mt < 2; mt++) {
                    mma16816(acc[mt][nt], ah[mt], bh0, bh1);
                    mma16816(acc[mt][nt], ah[mt], bl0, bl1);
                    mma16816(acc[mt][nt], al[mt], bh0, bh1);
                }
            }
        }
        __syncthreads();
    }

    // =============== fused epilogue: t1/t2, softmax(axis=i), output ===============
    // smem reuse (tiles are dead; all threads past the final sync)
    float* eS1P = reinterpret_cast<float*>(smem + OFF_AH);            // [128][2]
    float* eS2P = reinterpret_cast<float*>(smem + OFF_AH + 1024);     // [128][2]
    float* eS1F = reinterpret_cast<float*>(smem + OFF_AH + 2048);     // [128]
    float* eS2F = reinterpret_cast<float*>(smem + OFF_AH + 2560);     // [128]
    float* eMX2 = reinterpret_cast<float*>(smem + OFF_AH + 3072);     // [128][2]
    float* eZ2  = reinterpret_cast<float*>(smem + OFF_AH + 4096);     // [128][2]
    float* eMX  = reinterpret_cast<float*>(smem + OFF_AH + 5120);     // [128]
    float* eRZ  = reinterpret_cast<float*>(smem + OFF_AH + 5632);     // [128]

    // (a) per-thread fragment dots with Wb/Wc
    float s1p[4] = {0.f, 0.f, 0.f, 0.f}, s2p[4] = {0.f, 0.f, 0.f, 0.f};
    #pragma unroll
    for (int nt = 0; nt < 8; nt++) {
        int c = wn * 64 + nt * 8 + 2 * tig;
        float wb0 = __ldg(Wbv + c), wb1 = __ldg(Wbv + c + 1);
        float wc0 = __ldg(Wcv + c), wc1 = __ldg(Wcv + c + 1);
        #pragma unroll
        for (int mt = 0; mt < 2; mt++) {
            s1p[mt * 2 + 0] += acc[mt][nt][0] * wb0 + acc[mt][nt][1] * wb1;
            s1p[mt * 2 + 1] += acc[mt][nt][2] * wb0 + acc[mt][nt][3] * wb1;
            s2p[mt * 2 + 0] += acc[mt][nt][0] * wc0 + acc[mt][nt][1] * wc1;
            s2p[mt * 2 + 1] += acc[mt][nt][2] * wc0 + acc[mt][nt][3] * wc1;
        }
    }
    // (b) reduce over tig (lanes g*4+tig, xor 1 and 2 stay within group)
    #pragma unroll
    for (int off = 1; off <= 2; off <<= 1) {
        #pragma unroll
        for (int q = 0; q < 4; q++) {
            s1p[q] += __shfl_xor_sync(0xffffffffu, s1p[q], off);
            s2p[q] += __shfl_xor_sync(0xffffffffu, s2p[q], off);
        }
    }
    // (c) tig==0 lanes publish partials per row per wn
    if (tig == 0) {
        #pragma unroll
        for (int q = 0; q < 4; q++) {
            int r = wm * 32 + (q >> 1) * 16 + (q & 1) * 8 + g;
            eS1P[r * 2 + wn] = s1p[q];
            eS2P[r * 2 + wn] = s2p[q];
        }
    }
    __syncthreads();
    // (d) finalize t1/t2 (+biases)
    if (tid < 128) {
        eS1F[tid] = eS1P[tid * 2] + eS1P[tid * 2 + 1] + bbv[0];
        eS2F[tid] = eS2P[tid * 2] + eS2P[tid * 2 + 1] + bcv[0];
    }
    __syncthreads();
    // (e) column softmax stats: 2 threads per column j, split i-range
    {
        const int j = tid & 127, half = tid >> 7;
        const float s2j = eS2F[j];
        float m = -1e30f;
        #pragma unroll 4
        for (int i = half * 64; i < half * 64 + 64; i++)
            m = fmaxf(m, lrelu(eS1F[i] + s2j));
        eMX2[j * 2 + half] = m;
        __syncthreads();
        const float mj = fmaxf(eMX2[j * 2], eMX2[j * 2 + 1]);
        float z = 0.f;
        #pragma unroll 4
        for (int i = half * 64; i < half * 64 + 64; i++)
            z += __expf(lrelu(eS1F[i] + s2j) - mj);
        eZ2[j * 2 + half] = z;
        if (half == 0) eMX[j] = mj;
        __syncthreads();
        if (tid < 128) eRZ[tid] = 1.f / (eZ2[tid * 2] + eZ2[tid * 2 + 1]);
        __syncthreads();
    }
    // (f) output: out[b,i,j] = h*(1+coef) + bias[j]
    const size_t ob = (size_t)blockIdx.x * Nn * DH;
    float s1r[4];
    #pragma unroll
    for (int q = 0; q < 4; q++)
        s1r[q] = eS1F[wm * 32 + (q >> 1) * 16 + (q & 1) * 8 + g];
    #pragma unroll
    for (int nt = 0; nt < 8; nt++) {
        const int c = wn * 64 + nt * 8 + 2 * tig;
        const float s2a = eS2F[c],  s2b = eS2F[c + 1];
        const float mxa = eMX[c],   mxb = eMX[c + 1];
        const float rza = eRZ[c],   rzb = eRZ[c + 1];
        const float bia = __ldg(bias + c), bib = __ldg(bias + c + 1);
        #pragma unroll
        for (int mt = 0; mt < 2; mt++) {
            #pragma unroll
            for (int u = 0; u < 2; u++) {         // u=0 row r, u=1 row r+8
                const int i = wm * 32 + mt * 16 + u * 8 + g;
                const float s1v = s1r[mt * 2 + u];
                const float ca = __expf(lrelu(s1v + s2a) - mxa) * rza;
                const float cb = __expf(lrelu(s1v + s2b) - mxb) * rzb;
                const float ha = acc[mt][nt][u * 2 + 0];
                const float hb = acc[mt][nt][u * 2 + 1];
                *reinterpret_cast<float2*>(&out[ob + (size_t)i * DH + c]) =
                    make_float2(fmaf(ca, ha, ha + bia), fmaf(cb, hb, hb + bib));
            }
        }
    }
}

// ===================== W transpose + bf16 hi/lo split =====================
__global__ void wsplit_kernel(const float* __restrict__ Wa)
{
    int idx = blockIdx.x * 256 + threadIdx.x;   // [n][k]
    int n = idx >> 11, k = idx & 2047;
    float x = Wa[(size_t)k * DH + n];
    __nv_bfloat16 h = __float2bfloat16_rn(x);
    g_whi[idx] = h;
    g_wlo[idx] = __float2bfloat16_rn(x - __bfloat162float(h));
}

// ===================== launch =====================
typedef CUresult (*tmap_encode_t)(CUtensorMap*, CUtensorMapDataType, cuuint32_t, void*,
                                  const cuuint64_t*, const cuuint64_t*, const cuuint32_t*,
                                  const cuuint32_t*, CUtensorMapInterleave, CUtensorMapSwizzle,
                                  CUtensorMapL2promotion, CUtensorMapFloatOOBfill);

extern "C" void kernel_launch(void* const* d_in, const int* in_sizes, int n_in,
                              void* d_out, int out_size)
{
    const float* X    = (const float*)d_in[0];
    const float* Wa   = (const float*)d_in[1];
    const float* Wb   = (const float*)d_in[2];
    const float* bb   = (const float*)d_in[3];
    const float* Wc   = (const float*)d_in[4];
    const float* bc   = (const float*)d_in[5];
    const float* bias = (const float*)d_in[6];
    float* out = (float*)d_out;

    tmap_encode_t enc = nullptr;
    cudaDriverEntryPointQueryResult qr;
    cudaGetDriverEntryPointByVersion("cuTensorMapEncodeTiled", (void**)&enc, 12000,
                                     cudaEnableDefault, &qr);
    CUtensorMap mapA;
    {
        cuuint64_t dims[2]    = {Dd, Mtot};
        cuuint64_t strides[1] = {Dd * sizeof(float)};
        cuuint32_t box[2]     = {KC, 128};
        cuuint32_t es[2]      = {1, 1};
        enc(&mapA, CU_TENSOR_MAP_DATA_TYPE_FLOAT32, 2, (void*)X, dims, strides, box, es,
            CU_TENSOR_MAP_INTERLEAVE_NONE, CU_TENSOR_MAP_SWIZZLE_NONE,
            CU_TENSOR_MAP_L2_PROMOTION_L2_128B, CU_TENSOR_MAP_FLOAT_OOB_FILL_NONE);
    }

    wsplit_kernel<<<(Dd * DH) / 256, 256>>>(Wa);

    cudaFuncSetAttribute(fused_gat, cudaFuncAttributeMaxDynamicSharedMemorySize, SMEMSZ);
    fused_gat<<<Bb, 256, SMEMSZ>>>(Wb, bb, Wc, bc, bias, out, mapA);
}

// round 6
// speedup vs baseline: 23.6201x; 1.3718x over previous
#include <cuda_runtime.h>
#include <cuda.h>
#include <cuda_fp16.h>
#include <cstdint>

#define Bb   256
#define Nn   128
#define Dd   2048
#define DH   128
#define Mtot (Bb*Nn)   // 32768

// Scratch (device globals — no allocations allowed)
__device__ __align__(1024) __half g_wh[(size_t)DH * Dd];   // W^T fp16 [n][k], 512 KB

// ===================== PTX helpers =====================
__device__ __forceinline__ uint32_t smem_u32(const void* p) {
    uint32_t a;
    asm("{ .reg .u64 t; cvta.to.shared.u64 t, %1; cvt.u32.u64 %0, t; }" : "=r"(a) : "l"(p));
    return a;
}
__device__ __forceinline__ void mbar_init(uint32_t m, uint32_t cnt) {
    asm volatile("mbarrier.init.shared.b64 [%0], %1;" :: "r"(m), "r"(cnt) : "memory");
}
__device__ __forceinline__ void mbar_expect_tx(uint32_t m, uint32_t bytes) {
    asm volatile("mbarrier.arrive.expect_tx.shared.b64 _, [%0], %1;" :: "r"(m), "r"(bytes) : "memory");
}
__device__ __forceinline__ void mbar_wait(uint32_t m, uint32_t ph) {
    asm volatile(
        "{\n\t.reg .pred P;\n"
        "W%=:\n\t"
        "mbarrier.try_wait.parity.acquire.cta.shared::cta.b64 P, [%0], %1, 0x989680;\n\t"
        "@P bra D%=;\n\t"
        "bra W%=;\n"
        "D%=:\n\t}"
        :: "r"(m), "r"(ph) : "memory");
}
__device__ __forceinline__ void tma2d(uint32_t dst, const CUtensorMap* map, int x, int y, uint32_t mbar) {
    asm volatile(
        "cp.async.bulk.tensor.2d.shared::cta.global.tile.mbarrier::complete_tx::bytes "
        "[%0], [%1, {%2, %3}], [%4];"
        :: "r"(dst), "l"(map), "r"(x), "r"(y), "r"(mbar) : "memory");
}
__device__ __forceinline__ void mma16816(float* d, const uint32_t* a, uint32_t b0, uint32_t b1) {
    asm volatile(
        "mma.sync.aligned.m16n8k16.row.col.f32.f16.f16.f32 "
        "{%0,%1,%2,%3}, {%4,%5,%6,%7}, {%8,%9}, {%0,%1,%2,%3};"
        : "+f"(d[0]), "+f"(d[1]), "+f"(d[2]), "+f"(d[3])
        : "r"(a[0]), "r"(a[1]), "r"(a[2]), "r"(a[3]), "r"(b0), "r"(b1));
}
__device__ __forceinline__ float lrelu(float s) { return s > 0.f ? s : 0.2f * s; }

// ===================== config =====================
#define KC        32
#define NTILE     (Dd / KC)               // 64
#define STAGES    4
#define FPA_STAGE (128 * KC * 4)          // 16384 B fp32 A tile
#define AROW      80                      // padded fp16 row stride, 16B-aligned, conflict-free
#define TILE16    (128 * AROW)            // 10240 B per fp16 tile
#define OFF_FPA   1024
#define OFF_AH    (OFF_FPA + STAGES * FPA_STAGE)   // 66560
#define OFF_AL    (OFF_AH + TILE16)                // 76800
#define OFF_B     (OFF_AL + TILE16)                // 87040
#define SMEMSZ    (OFF_B + TILE16)                 // 97280 -> 2 CTAs/SM

__global__ void __launch_bounds__(256, 2)
fused_gat(const float* __restrict__ Wbv, const float* __restrict__ bbv,
          const float* __restrict__ Wcv, const float* __restrict__ bcv,
          const float* __restrict__ bias, float* __restrict__ out,
          const __grid_constant__ CUtensorMap mapA)
{
    extern __shared__ char smem[];
    const uint32_t sb = smem_u32(smem);
    const int tid = threadIdx.x;
    const int lane = tid & 31, w = tid >> 5;
    const int g = lane >> 2, tig = lane & 3;
    const int wm = w & 3;        // m-block (32 rows)
    const int wn = w >> 2;       // n-block (64 cols)

    if (tid == 0) {
        #pragma unroll
        for (int s = 0; s < STAGES; s++) mbar_init(sb + 8 * s, 1);
    }
    __syncthreads();
    if (tid == 0) {
        #pragma unroll
        for (int s = 0; s < STAGES; s++) {
            mbar_expect_tx(sb + 8 * s, FPA_STAGE);
            tma2d(sb + OFF_FPA + s * FPA_STAGE, &mapA, s * KC, blockIdx.x * 128, sb + 8 * s);
        }
    }

    float acc[2][8][4];
    #pragma unroll
    for (int mt = 0; mt < 2; mt++)
        #pragma unroll
        for (int nt = 0; nt < 8; nt++)
            #pragma unroll
            for (int q = 0; q < 4; q++) acc[mt][nt][q] = 0.f;

    #pragma unroll 1
    for (int t = 0; t < NTILE; t++) {
        const int st = t & (STAGES - 1);
        const uint32_t ph = (t / STAGES) & 1;

        // B: global fp16 loads (L2-resident), 2 float4 per thread
        float4 bgl[2];
        #pragma unroll
        for (int i = 0; i < 2; i++) {
            int f = tid + i * 256;
            int n = f >> 2, kq = f & 3;
            size_t byt = (size_t)n * (Dd * 2) + (size_t)t * (KC * 2) + kq * 16;
            bgl[i] = *reinterpret_cast<const float4*>(reinterpret_cast<const char*>(g_wh) + byt);
        }

        mbar_wait(sb + 8 * st, ph);

        // A: fp32 -> fp16 hi/lo (smem -> regs -> smem)
        const float4* fa = reinterpret_cast<const float4*>(smem + OFF_FPA + st * FPA_STAGE);
        float4 xr[4];
        #pragma unroll
        for (int i = 0; i < 4; i++) xr[i] = fa[tid + i * 256];

        __syncthreads();   // previous tile's MMA done reading fp16 tiles

        #pragma unroll
        for (int i = 0; i < 4; i++) {
            int f = tid + i * 256;
            int m = f >> 3, kq = f & 7;
            float4 x = xr[i];
            __half2 h0 = __float22half2_rn(make_float2(x.x, x.y));
            __half2 h1 = __float22half2_rn(make_float2(x.z, x.w));
            float2 hf0 = __half22float2(h0);
            float2 hf1 = __half22float2(h1);
            __half2 l0 = __float22half2_rn(make_float2(x.x - hf0.x, x.y - hf0.y));
            __half2 l1 = __float22half2_rn(make_float2(x.z - hf1.x, x.w - hf1.y));
            uint32_t off = (uint32_t)m * AROW + (uint32_t)kq * 8;
            *reinterpret_cast<uint2*>(smem + OFF_AH + off) =
                make_uint2(*reinterpret_cast<uint32_t*>(&h0), *reinterpret_cast<uint32_t*>(&h1));
            *reinterpret_cast<uint2*>(smem + OFF_AL + off) =
                make_uint2(*reinterpret_cast<uint32_t*>(&l0), *reinterpret_cast<uint32_t*>(&l1));
        }
        #pragma unroll
        for (int i = 0; i < 2; i++) {
            int f = tid + i * 256;
            int n = f >> 2, kq = f & 3;
            *reinterpret_cast<float4*>(smem + OFF_B + (uint32_t)n * AROW + (uint32_t)kq * 16) = bgl[i];
        }
        __syncthreads();

        // refill the fp32 stage just consumed
        if (tid == 0 && t + STAGES < NTILE) {
            mbar_expect_tx(sb + 8 * st, FPA_STAGE);
            tma2d(sb + OFF_FPA + st * FPA_STAGE, &mapA, (t + STAGES) * KC, blockIdx.x * 128, sb + 8 * st);
        }

        // MMA: 2 k16 steps, 2m x 8n, 2 passes (hi, lo)
        #pragma unroll
        for (int s = 0; s < 2; s++) {
            uint32_t ah[2][4], al[2][4];
            #pragma unroll
            for (int mt = 0; mt < 2; mt++) {
                const char* base = smem + OFF_AH + (wm * 32 + mt * 16 + g) * AROW + s * 32 + tig * 4;
                ah[mt][0] = *reinterpret_cast<const uint32_t*>(base);
                ah[mt][1] = *reinterpret_cast<const uint32_t*>(base + 8 * AROW);
                ah[mt][2] = *reinterpret_cast<const uint32_t*>(base + 16);
                ah[mt][3] = *reinterpret_cast<const uint32_t*>(base + 8 * AROW + 16);
                const char* basl = base + (OFF_AL - OFF_AH);
                al[mt][0] = *reinterpret_cast<const uint32_t*>(basl);
                al[mt][1] = *reinterpret_cast<const uint32_t*>(basl + 8 * AROW);
                al[mt][2] = *reinterpret_cast<const uint32_t*>(basl + 16);
                al[mt][3] = *reinterpret_cast<const uint32_t*>(basl + 8 * AROW + 16);
            }
            #pragma unroll
            for (int nt = 0; nt < 8; nt++) {
                const char* nb = smem + OFF_B + (wn * 64 + nt * 8 + g) * AROW + s * 32 + tig * 4;
                uint32_t b0 = *reinterpret_cast<const uint32_t*>(nb);
                uint32_t b1 = *reinterpret_cast<const uint32_t*>(nb + 16);
                #pragma unroll
                for (int mt = 0; mt < 2; mt++) {
                    mma16816(acc[mt][nt], ah[mt], b0, b1);
                    mma16816(acc[mt][nt], al[mt], b0, b1);
                }
            }
        }
    }
    __syncthreads();

    // =============== fused epilogue: t1/t2, softmax(axis=i), output ===============
    float* eS1P = reinterpret_cast<float*>(smem + OFF_AH);            // [128][2]
    float* eS2P = reinterpret_cast<float*>(smem + OFF_AH + 1024);     // [128][2]
    float* eS1F = reinterpret_cast<float*>(smem + OFF_AH + 2048);     // [128]
    float* eS2F = reinterpret_cast<float*>(smem + OFF_AH + 2560);     // [128]
    float* eMX2 = reinterpret_cast<float*>(smem + OFF_AH + 3072);     // [128][2]
    float* eZ2  = reinterpret_cast<float*>(smem + OFF_AH + 4096);     // [128][2]
    float* eMX  = reinterpret_cast<float*>(smem + OFF_AH + 5120);     // [128]
    float* eRZ  = reinterpret_cast<float*>(smem + OFF_AH + 5632);     // [128]

    // (a) per-thread fragment dots with Wb/Wc
    float s1p[4] = {0.f, 0.f, 0.f, 0.f}, s2p[4] = {0.f, 0.f, 0.f, 0.f};
    #pragma unroll
    for (int nt = 0; nt < 8; nt++) {
        int c = wn * 64 + nt * 8 + 2 * tig;
        float wb0 = __ldg(Wbv + c), wb1 = __ldg(Wbv + c + 1);
        float wc0 = __ldg(Wcv + c), wc1 = __ldg(Wcv + c + 1);
        #pragma unroll
        for (int mt = 0; mt < 2; mt++) {
            s1p[mt * 2 + 0] += acc[mt][nt][0] * wb0 + acc[mt][nt][1] * wb1;
            s1p[mt * 2 + 1] += acc[mt][nt][2] * wb0 + acc[mt][nt][3] * wb1;
            s2p[mt * 2 + 0] += acc[mt][nt][0] * wc0 + acc[mt][nt][1] * wc1;
            s2p[mt * 2 + 1] += acc[mt][nt][2] * wc0 + acc[mt][nt][3] * wc1;
        }
    }
    // (b) reduce over tig
    #pragma unroll
    for (int off = 1; off <= 2; off <<= 1) {
        #pragma unroll
        for (int q = 0; q < 4; q++) {
            s1p[q] += __shfl_xor_sync(0xffffffffu, s1p[q], off);
            s2p[q] += __shfl_xor_sync(0xffffffffu, s2p[q], off);
        }
    }
    // (c) publish per-row partials per wn
    if (tig == 0) {
        #pragma unroll
        for (int q = 0; q < 4; q++) {
            int r = wm * 32 + (q >> 1) * 16 + (q & 1) * 8 + g;
            eS1P[r * 2 + wn] = s1p[q];
            eS2P[r * 2 + wn] = s2p[q];
        }
    }
    __syncthreads();
    // (d) finalize t1/t2
    if (tid < 128) {
        eS1F[tid] = eS1P[tid * 2] + eS1P[tid * 2 + 1] + bbv[0];
        eS2F[tid] = eS2P[tid * 2] + eS2P[tid * 2 + 1] + bcv[0];
    }
    __syncthreads();
    // (e) column softmax stats
    {
        const int j = tid & 127, half = tid >> 7;
        const float s2j = eS2F[j];
        float m = -1e30f;
        #pragma unroll 4
        for (int i = half * 64; i < half * 64 + 64; i++)
            m = fmaxf(m, lrelu(eS1F[i] + s2j));
        eMX2[j * 2 + half] = m;
        __syncthreads();
        const float mj = fmaxf(eMX2[j * 2], eMX2[j * 2 + 1]);
        float z = 0.f;
        #pragma unroll 4
        for (int i = half * 64; i < half * 64 + 64; i++)
            z += __expf(lrelu(eS1F[i] + s2j) - mj);
        eZ2[j * 2 + half] = z;
        if (half == 0) eMX[j] = mj;
        __syncthreads();
        if (tid < 128) eRZ[tid] = 1.f / (eZ2[tid * 2] + eZ2[tid * 2 + 1]);
        __syncthreads();
    }
    // (f) output
    const size_t ob = (size_t)blockIdx.x * Nn * DH;
    float s1r[4];
    #pragma unroll
    for (int q = 0; q < 4; q++)
        s1r[q] = eS1F[wm * 32 + (q >> 1) * 16 + (q & 1) * 8 + g];
    #pragma unroll
    for (int nt = 0; nt < 8; nt++) {
        const int c = wn * 64 + nt * 8 + 2 * tig;
        const float s2a = eS2F[c],  s2b = eS2F[c + 1];
        const float mxa = eMX[c],   mxb = eMX[c + 1];
        const float rza = eRZ[c],   rzb = eRZ[c + 1];
        const float bia = __ldg(bias + c), bib = __ldg(bias + c + 1);
        #pragma unroll
        for (int mt = 0; mt < 2; mt++) {
            #pragma unroll
            for (int u = 0; u < 2; u++) {
                const int i = wm * 32 + mt * 16 + u * 8 + g;
                const float s1v = s1r[mt * 2 + u];
                const float ca = __expf(lrelu(s1v + s2a) - mxa) * rza;
                const float cb = __expf(lrelu(s1v + s2b) - mxb) * rzb;
                const float ha = acc[mt][nt][u * 2 + 0];
                const float hb = acc[mt][nt][u * 2 + 1];
                *reinterpret_cast<float2*>(&out[ob + (size_t)i * DH + c]) =
                    make_float2(fmaf(ca, ha, ha + bia), fmaf(cb, hb, hb + bib));
            }
        }
    }
}

// ===================== W transpose -> fp16 =====================
__global__ void wsplit_kernel(const float* __restrict__ Wa)
{
    int idx = blockIdx.x * 256 + threadIdx.x;   // [n][k]
    int n = idx >> 11, k = idx & 2047;
    g_wh[idx] = __float2half_rn(Wa[(size_t)k * DH + n]);
}

// ===================== launch =====================
typedef CUresult (*tmap_encode_t)(CUtensorMap*, CUtensorMapDataType, cuuint32_t, void*,
                                  const cuuint64_t*, const cuuint64_t*, const cuuint32_t*,
                                  const cuuint32_t*, CUtensorMapInterleave, CUtensorMapSwizzle,
                                  CUtensorMapL2promotion, CUtensorMapFloatOOBfill);

extern "C" void kernel_launch(void* const* d_in, const int* in_sizes, int n_in,
                              void* d_out, int out_size)
{
    const float* X    = (const float*)d_in[0];
    const float* Wa   = (const float*)d_in[1];
    const float* Wb   = (const float*)d_in[2];
    const float* bb   = (const float*)d_in[3];
    const float* Wc   = (const float*)d_in[4];
    const float* bc   = (const float*)d_in[5];
    const float* bias = (const float*)d_in[6];
    float* out = (float*)d_out;

    tmap_encode_t enc = nullptr;
    cudaDriverEntryPointQueryResult qr;
    cudaGetDriverEntryPointByVersion("cuTensorMapEncodeTiled", (void**)&enc, 12000,
                                     cudaEnableDefault, &qr);
    CUtensorMap mapA;
    {
        cuuint64_t dims[2]    = {Dd, Mtot};
        cuuint64_t strides[1] = {Dd * sizeof(float)};
        cuuint32_t box[2]     = {KC, 128};
        cuuint32_t es[2]      = {1, 1};
        enc(&mapA, CU_TENSOR_MAP_DATA_TYPE_FLOAT32, 2, (void*)X, dims, strides, box, es,
            CU_TENSOR_MAP_INTERLEAVE_NONE, CU_TENSOR_MAP_SWIZZLE_NONE,
            CU_TENSOR_MAP_L2_PROMOTION_L2_128B, CU_TENSOR_MAP_FLOAT_OOB_FILL_NONE);
    }

    wsplit_kernel<<<(Dd * DH) / 256, 256>>>(Wa);

    cudaFuncSetAttribute(fused_gat, cudaFuncAttributeMaxDynamicSharedMemorySize, SMEMSZ);
    fused_gat<<<Bb, 256, SMEMSZ>>>(Wb, bb, Wc, bc, bias, out, mapA);
}

// round 7
// speedup vs baseline: 33.0273x; 1.3983x over previous
#include <cuda_runtime.h>
#include <cuda.h>
#include <cuda_fp16.h>
#include <cstdint>

#define Bb   256
#define Nn   128
#define Dd   2048
#define DH   128
#define Mtot (Bb*Nn)   // 32768

// Scratch (device globals — no allocations allowed)
__device__ __align__(1024) __half g_wh[(size_t)DH * Dd];   // W^T fp16 [n][k], 512 KB

// ===================== PTX helpers =====================
__device__ __forceinline__ uint32_t smem_u32(const void* p) {
    uint32_t a;
    asm("{ .reg .u64 t; cvta.to.shared.u64 t, %1; cvt.u32.u64 %0, t; }" : "=r"(a) : "l"(p));
    return a;
}
__device__ __forceinline__ void mbar_init(uint32_t m, uint32_t cnt) {
    asm volatile("mbarrier.init.shared.b64 [%0], %1;" :: "r"(m), "r"(cnt) : "memory");
}
__device__ __forceinline__ void mbar_expect_tx(uint32_t m, uint32_t bytes) {
    asm volatile("mbarrier.arrive.expect_tx.shared.b64 _, [%0], %1;" :: "r"(m), "r"(bytes) : "memory");
}
__device__ __forceinline__ void mbar_wait(uint32_t m, uint32_t ph) {
    asm volatile(
        "{\n\t.reg .pred P;\n"
        "W%=:\n\t"
        "mbarrier.try_wait.parity.acquire.cta.shared::cta.b64 P, [%0], %1, 0x989680;\n\t"
        "@P bra D%=;\n\t"
        "bra W%=;\n"
        "D%=:\n\t}"
        :: "r"(m), "r"(ph) : "memory");
}
__device__ __forceinline__ void tma2d(uint32_t dst, const CUtensorMap* map, int x, int y, uint32_t mbar) {
    asm volatile(
        "cp.async.bulk.tensor.2d.shared::cta.global.tile.mbarrier::complete_tx::bytes "
        "[%0], [%1, {%2, %3}], [%4];"
        :: "r"(dst), "l"(map), "r"(x), "r"(y), "r"(mbar) : "memory");
}
__device__ __forceinline__ void mma16816(float* d, const uint32_t* a, uint32_t b0, uint32_t b1) {
    asm volatile(
        "mma.sync.aligned.m16n8k16.row.col.f32.f16.f16.f32 "
        "{%0,%1,%2,%3}, {%4,%5,%6,%7}, {%8,%9}, {%0,%1,%2,%3};"
        : "+f"(d[0]), "+f"(d[1]), "+f"(d[2]), "+f"(d[3])
        : "r"(a[0]), "r"(a[1]), "r"(a[2]), "r"(a[3]), "r"(b0), "r"(b1));
}
__device__ __forceinline__ float lrelu(float s) { return s > 0.f ? s : 0.2f * s; }

// ===================== config =====================
#define KC        32
#define NTILE     (Dd / KC)               // 64
#define STAGES    4
#define FPA_STAGE (128 * KC * 4)          // 16384 B fp32 A tile
#define AROW      80                      // padded fp16 row stride, 16B-aligned, conflict-free
#define TILE16    (128 * AROW)            // 10240 B per fp16 tile
#define OFF_FPA   1024
#define OFF_AH    (OFF_FPA + STAGES * FPA_STAGE)   // 66560
#define OFF_B     (OFF_AH + TILE16)                // 76800
#define SMEMSZ    (OFF_B + TILE16)                 // 87040 -> 2 CTAs/SM

__global__ void __launch_bounds__(256, 2)
fused_gat(const float* __restrict__ Wbv, const float* __restrict__ bbv,
          const float* __restrict__ Wcv, const float* __restrict__ bcv,
          const float* __restrict__ bias, float* __restrict__ out,
          const __grid_constant__ CUtensorMap mapA)
{
    extern __shared__ char smem[];
    const uint32_t sb = smem_u32(smem);
    const int tid = threadIdx.x;
    const int lane = tid & 31, w = tid >> 5;
    const int g = lane >> 2, tig = lane & 3;
    const int wm = w & 3;        // m-block (32 rows)
    const int wn = w >> 2;       // n-block (64 cols)

    if (tid == 0) {
        #pragma unroll
        for (int s = 0; s < STAGES; s++) mbar_init(sb + 8 * s, 1);
    }
    __syncthreads();
    if (tid == 0) {
        #pragma unroll
        for (int s = 0; s < STAGES; s++) {
            mbar_expect_tx(sb + 8 * s, FPA_STAGE);
            tma2d(sb + OFF_FPA + s * FPA_STAGE, &mapA, s * KC, blockIdx.x * 128, sb + 8 * s);
        }
    }

    float acc[2][8][4];
    #pragma unroll
    for (int mt = 0; mt < 2; mt++)
        #pragma unroll
        for (int nt = 0; nt < 8; nt++)
            #pragma unroll
            for (int q = 0; q < 4; q++) acc[mt][nt][q] = 0.f;

    #pragma unroll 1
    for (int t = 0; t < NTILE; t++) {
        const int st = t & (STAGES - 1);
        const uint32_t ph = (t / STAGES) & 1;

        // B: global fp16 loads (L2-resident), 2 float4 per thread
        float4 bgl[2];
        #pragma unroll
        for (int i = 0; i < 2; i++) {
            int f = tid + i * 256;
            int n = f >> 2, kq = f & 3;
            size_t byt = (size_t)n * (Dd * 2) + (size_t)t * (KC * 2) + kq * 16;
            bgl[i] = *reinterpret_cast<const float4*>(reinterpret_cast<const char*>(g_wh) + byt);
        }

        mbar_wait(sb + 8 * st, ph);

        // A: fp32 -> fp16 (smem -> regs -> smem)
        const float4* fa = reinterpret_cast<const float4*>(smem + OFF_FPA + st * FPA_STAGE);
        float4 xr[4];
        #pragma unroll
        for (int i = 0; i < 4; i++) xr[i] = fa[tid + i * 256];

        __syncthreads();   // previous tile's MMA done reading fp16 tiles

        #pragma unroll
        for (int i = 0; i < 4; i++) {
            int f = tid + i * 256;
            int m = f >> 3, kq = f & 7;
            float4 x = xr[i];
            __half2 h0 = __float22half2_rn(make_float2(x.x, x.y));
            __half2 h1 = __float22half2_rn(make_float2(x.z, x.w));
            uint32_t off = (uint32_t)m * AROW + (uint32_t)kq * 8;
            *reinterpret_cast<uint2*>(smem + OFF_AH + off) =
                make_uint2(*reinterpret_cast<uint32_t*>(&h0), *reinterpret_cast<uint32_t*>(&h1));
        }
        #pragma unroll
        for (int i = 0; i < 2; i++) {
            int f = tid + i * 256;
            int n = f >> 2, kq = f & 3;
            *reinterpret_cast<float4*>(smem + OFF_B + (uint32_t)n * AROW + (uint32_t)kq * 16) = bgl[i];
        }
        __syncthreads();

        // refill the fp32 stage just consumed
        if (tid == 0 && t + STAGES < NTILE) {
            mbar_expect_tx(sb + 8 * st, FPA_STAGE);
            tma2d(sb + OFF_FPA + st * FPA_STAGE, &mapA, (t + STAGES) * KC, blockIdx.x * 128, sb + 8 * st);
        }

        // MMA: 2 k16 steps, 2m x 8n, single fp16 pass
        #pragma unroll
        for (int s = 0; s < 2; s++) {
            uint32_t ah[2][4];
            #pragma unroll
            for (int mt = 0; mt < 2; mt++) {
                const char* base = smem + OFF_AH + (wm * 32 + mt * 16 + g) * AROW + s * 32 + tig * 4;
                ah[mt][0] = *reinterpret_cast<const uint32_t*>(base);
                ah[mt][1] = *reinterpret_cast<const uint32_t*>(base + 8 * AROW);
                ah[mt][2] = *reinterpret_cast<const uint32_t*>(base + 16);
                ah[mt][3] = *reinterpret_cast<const uint32_t*>(base + 8 * AROW + 16);
            }
            #pragma unroll
            for (int nt = 0; nt < 8; nt++) {
                const char* nb = smem + OFF_B + (wn * 64 + nt * 8 + g) * AROW + s * 32 + tig * 4;
                uint32_t b0 = *reinterpret_cast<const uint32_t*>(nb);
                uint32_t b1 = *reinterpret_cast<const uint32_t*>(nb + 16);
                #pragma unroll
                for (int mt = 0; mt < 2; mt++)
                    mma16816(acc[mt][nt], ah[mt], b0, b1);
            }
        }
    }
    __syncthreads();

    // =============== fused epilogue: t1/t2, softmax(axis=i), output ===============
    float* eS1P = reinterpret_cast<float*>(smem + OFF_AH);            // [128][2]
    float* eS2P = reinterpret_cast<float*>(smem + OFF_AH + 1024);     // [128][2]
    float* eS1F = reinterpret_cast<float*>(smem + OFF_AH + 2048);     // [128]
    float* eS2F = reinterpret_cast<float*>(smem + OFF_AH + 2560);     // [128]
    float* eMX2 = reinterpret_cast<float*>(smem + OFF_AH + 3072);     // [128][2]
    float* eZ2  = reinterpret_cast<float*>(smem + OFF_AH + 4096);     // [128][2]
    float* eMX  = reinterpret_cast<float*>(smem + OFF_AH + 5120);     // [128]
    float* eRZ  = reinterpret_cast<float*>(smem + OFF_AH + 5632);     // [128]

    // (a) per-thread fragment dots with Wb/Wc
    float s1p[4] = {0.f, 0.f, 0.f, 0.f}, s2p[4] = {0.f, 0.f, 0.f, 0.f};
    #pragma unroll
    for (int nt = 0; nt < 8; nt++) {
        int c = wn * 64 + nt * 8 + 2 * tig;
        float wb0 = __ldg(Wbv + c), wb1 = __ldg(Wbv + c + 1);
        float wc0 = __ldg(Wcv + c), wc1 = __ldg(Wcv + c + 1);
        #pragma unroll
        for (int mt = 0; mt < 2; mt++) {
            s1p[mt * 2 + 0] += acc[mt][nt][0] * wb0 + acc[mt][nt][1] * wb1;
            s1p[mt * 2 + 1] += acc[mt][nt][2] * wb0 + acc[mt][nt][3] * wb1;
            s2p[mt * 2 + 0] += acc[mt][nt][0] * wc0 + acc[mt][nt][1] * wc1;
            s2p[mt * 2 + 1] += acc[mt][nt][2] * wc0 + acc[mt][nt][3] * wc1;
        }
    }
    // (b) reduce over tig
    #pragma unroll
    for (int off = 1; off <= 2; off <<= 1) {
        #pragma unroll
        for (int q = 0; q < 4; q++) {
            s1p[q] += __shfl_xor_sync(0xffffffffu, s1p[q], off);
            s2p[q] += __shfl_xor_sync(0xffffffffu, s2p[q], off);
        }
    }
    // (c) publish per-row partials per wn
    if (tig == 0) {
        #pragma unroll
        for (int q = 0; q < 4; q++) {
            int r = wm * 32 + (q >> 1) * 16 + (q & 1) * 8 + g;
            eS1P[r * 2 + wn] = s1p[q];
            eS2P[r * 2 + wn] = s2p[q];
        }
    }
    __syncthreads();
    // (d) finalize t1/t2
    if (tid < 128) {
        eS1F[tid] = eS1P[tid * 2] + eS1P[tid * 2 + 1] + bbv[0];
        eS2F[tid] = eS2P[tid * 2] + eS2P[tid * 2 + 1] + bcv[0];
    }
    __syncthreads();
    // (e) column softmax stats
    {
        const int j = tid & 127, half = tid >> 7;
        const float s2j = eS2F[j];
        float m = -1e30f;
        #pragma unroll 4
        for (int i = half * 64; i < half * 64 + 64; i++)
            m = fmaxf(m, lrelu(eS1F[i] + s2j));
        eMX2[j * 2 + half] = m;
        __syncthreads();
        const float mj = fmaxf(eMX2[j * 2], eMX2[j * 2 + 1]);
        float z = 0.f;
        #pragma unroll 4
        for (int i = half * 64; i < half * 64 + 64; i++)
            z += __expf(lrelu(eS1F[i] + s2j) - mj);
        eZ2[j * 2 + half] = z;
        if (half == 0) eMX[j] = mj;
        __syncthreads();
        if (tid < 128) eRZ[tid] = 1.f / (eZ2[tid * 2] + eZ2[tid * 2 + 1]);
        __syncthreads();
    }
    // (f) output
    const size_t ob = (size_t)blockIdx.x * Nn * DH;
    float s1r[4];
    #pragma unroll
    for (int q = 0; q < 4; q++)
        s1r[q] = eS1F[wm * 32 + (q >> 1) * 16 + (q & 1) * 8 + g];
    #pragma unroll
    for (int nt = 0; nt < 8; nt++) {
        const int c = wn * 64 + nt * 8 + 2 * tig;
        const float s2a = eS2F[c],  s2b = eS2F[c + 1];
        const float mxa = eMX[c],   mxb = eMX[c + 1];
        const float rza = eRZ[c],   rzb = eRZ[c + 1];
        const float bia = __ldg(bias + c), bib = __ldg(bias + c + 1);
        #pragma unroll
        for (int mt = 0; mt < 2; mt++) {
            #pragma unroll
            for (int u = 0; u < 2; u++) {
                const int i = wm * 32 + mt * 16 + u * 8 + g;
                const float s1v = s1r[mt * 2 + u];
                const float ca = __expf(lrelu(s1v + s2a) - mxa) * rza;
                const float cb = __expf(lrelu(s1v + s2b) - mxb) * rzb;
                const float ha = acc[mt][nt][u * 2 + 0];
                const float hb = acc[mt][nt][u * 2 + 1];
                *reinterpret_cast<float2*>(&out[ob + (size_t)i * DH + c]) =
                    make_float2(fmaf(ca, ha, ha + bia), fmaf(cb, hb, hb + bib));
            }
        }
    }
}

// ===================== W transpose -> fp16 =====================
__global__ void wsplit_kernel(const float* __restrict__ Wa)
{
    int idx = blockIdx.x * 256 + threadIdx.x;   // [n][k]
    int n = idx >> 11, k = idx & 2047;
    g_wh[idx] = __float2half_rn(Wa[(size_t)k * DH + n]);
}

// ===================== launch =====================
typedef CUresult (*tmap_encode_t)(CUtensorMap*, CUtensorMapDataType, cuuint32_t, void*,
                                  const cuuint64_t*, const cuuint64_t*, const cuuint32_t*,
                                  const cuuint32_t*, CUtensorMapInterleave, CUtensorMapSwizzle,
                                  CUtensorMapL2promotion, CUtensorMapFloatOOBfill);

extern "C" void kernel_launch(void* const* d_in, const int* in_sizes, int n_in,
                              void* d_out, int out_size)
{
    const float* X    = (const float*)d_in[0];
    const float* Wa   = (const float*)d_in[1];
    const float* Wb   = (const float*)d_in[2];
    const float* bb   = (const float*)d_in[3];
    const float* Wc   = (const float*)d_in[4];
    const float* bc   = (const float*)d_in[5];
    const float* bias = (const float*)d_in[6];
    float* out = (float*)d_out;

    tmap_encode_t enc = nullptr;
    cudaDriverEntryPointQueryResult qr;
    cudaGetDriverEntryPointByVersion("cuTensorMapEncodeTiled", (void**)&enc, 12000,
                                     cudaEnableDefault, &qr);
    CUtensorMap mapA;
    {
        cuuint64_t dims[2]    = {Dd, Mtot};
        cuuint64_t strides[1] = {Dd * sizeof(float)};
        cuuint32_t box[2]     = {KC, 128};
        cuuint32_t es[2]      = {1, 1};
        enc(&mapA, CU_TENSOR_MAP_DATA_TYPE_FLOAT32, 2, (void*)X, dims, strides, box, es,
            CU_TENSOR_MAP_INTERLEAVE_NONE, CU_TENSOR_MAP_SWIZZLE_NONE,
            CU_TENSOR_MAP_L2_PROMOTION_L2_128B, CU_TENSOR_MAP_FLOAT_OOB_FILL_NONE);
    }

    wsplit_kernel<<<(Dd * DH) / 256, 256>>>(Wa);

    cudaFuncSetAttribute(fused_gat, cudaFuncAttributeMaxDynamicSharedMemorySize, SMEMSZ);
    fused_gat<<<Bb, 256, SMEMSZ>>>(Wb, bb, Wc, bc, bias, out, mapA);
}